// round 16
// baseline (speedup 1.0000x reference)
#include <cuda_runtime.h>
#include <cuda_fp16.h>
#include <stdint.h>

#define NA 131072
#define NE 524288
#define NM 2048
#define GG 50
#define NBINS 4096
#define DCUT 6.0f
#define LN2F 0.69314718056f
#define ASTR 68  // u32 words per smem row (64 data + 4 pad); 68 % 32 == 4 -> conflict-free

// ---- device scratch ----
__device__ __half g_rh[NA * 128];        // fp16 residual stream r
__device__ __half g_hbuf[2][NA * 128];   // double-buffered h (fixes cross-CTA race)
__device__ __half g_wH[10 * 128 * 128];  // transposed fp16 weights [m][n][k]
__device__ __half g_tableH[3 * (NBINS + 1) * 128];
__device__ __half g_tabP[3 * NBINS * 256];  // paired rows {W(b), W(b+1)} per lane
__device__ float g_edge_d[NE];
__device__ int   g_deg[NA];
__device__ int   g_start[NA + 1];
__device__ int   g_cur[NA];
__device__ int   g_bsum[512];
__device__ int   g_slot_other[2 * NE];
__device__ float g_slot_pos[2 * NE];

__device__ __forceinline__ float sspf(float x) {
    return fmaxf(x, 0.f) + log1pf(__expf(-fabsf(x))) - LN2F;
}
__device__ __forceinline__ uint32_t pack_h2(float a, float b) {
    __half2 p = __floats2half2_rn(a, b);
    return *(uint32_t*)&p;
}
__device__ __forceinline__ void mma_f16(float* c, const uint32_t* a, const uint32_t* b) {
    asm volatile(
        "mma.sync.aligned.m16n8k16.row.col.f32.f16.f16.f32 "
        "{%0,%1,%2,%3}, {%4,%5,%6,%7}, {%8,%9}, {%0,%1,%2,%3};"
        : "+f"(c[0]), "+f"(c[1]), "+f"(c[2]), "+f"(c[3])
        : "r"(a[0]), "r"(a[1]), "r"(a[2]), "r"(a[3]), "r"(b[0]), "r"(b[1]));
}
__device__ __forceinline__ void ldsm_x4(uint32_t& r0, uint32_t& r1, uint32_t& r2,
                                        uint32_t& r3, uint32_t addr) {
    asm volatile("ldmatrix.sync.aligned.m8n8.x4.shared.b16 {%0,%1,%2,%3}, [%4];"
                 : "=r"(r0), "=r"(r1), "=r"(r2), "=r"(r3) : "r"(addr));
}

// ---- prep kernels ----
__global__ void k_prep(float* __restrict__ out) {
    int i = blockIdx.x * blockDim.x + threadIdx.x;
    if (i < NA) g_deg[i] = 0;
    if (i < NM) out[i] = 0.f;
}
__global__ void k_embed(const float* __restrict__ emb, const int* __restrict__ z) {
    int idx = blockIdx.x * blockDim.x + threadIdx.x;
    int atom = idx >> 5, q = idx & 31;
    float4 v = ((const float4*)emb)[(size_t)z[atom] * 32 + q];
    uint2 o;
    o.x = pack_h2(v.x, v.y);
    o.y = pack_h2(v.z, v.w);
    ((uint2*)g_rh)[(size_t)atom * 32 + q] = o;
}
__global__ void k_edge(const float* __restrict__ xyz, const int* __restrict__ a) {
    int e = blockIdx.x * blockDim.x + threadIdx.x;
    if (e >= NE) return;
    int i = a[2 * e], j = a[2 * e + 1];
    float dx = xyz[3 * i] - xyz[3 * j];
    float dy = xyz[3 * i + 1] - xyz[3 * j + 1];
    float dz = xyz[3 * i + 2] - xyz[3 * j + 2];
    float d = sqrtf(dx * dx + dy * dy + dz * dz);
    g_edge_d[e] = d;
    if (d < DCUT) { atomicAdd(&g_deg[i], 1); atomicAdd(&g_deg[j], 1); }
}
__global__ void k_scan1() {
    int b = blockIdx.x, t = threadIdx.x, i = b * 256 + t;
    int lane = t & 31, w = t >> 5;
    int v = g_deg[i], s = v;
#pragma unroll
    for (int off = 1; off < 32; off <<= 1) {
        int u = __shfl_up_sync(0xffffffffu, s, off);
        if (lane >= off) s += u;
    }
    __shared__ int wsum[8];
    if (lane == 31) wsum[w] = s;
    __syncthreads();
    if (t < 8) {
        int x = wsum[t];
#pragma unroll
        for (int off = 1; off < 8; off <<= 1) {
            int u = __shfl_up_sync(0xffu, x, off);
            if (t >= off) x += u;
        }
        wsum[t] = x;
    }
    __syncthreads();
    int base = (w > 0) ? wsum[w - 1] : 0;
    g_start[i] = base + s - v;
    if (t == 255) g_bsum[b] = wsum[7];
}
__global__ void k_scan2() {
    __shared__ int sh[512];
    int t = threadIdx.x;
    int v = g_bsum[t];
    sh[t] = v;
    __syncthreads();
    for (int off = 1; off < 512; off <<= 1) {
        int u = (t >= off) ? sh[t - off] : 0;
        __syncthreads();
        sh[t] += u;
        __syncthreads();
    }
    g_bsum[t] = sh[t] - v;
    if (t == 511) g_start[NA] = sh[511];
}
__global__ void k_scan3() {
    int b = blockIdx.x, i = b * 256 + threadIdx.x;
    int s = g_start[i] + g_bsum[b];
    g_start[i] = s;
    g_cur[i] = s;
}
__global__ void k_fill(const int* __restrict__ a) {
    int e = blockIdx.x * blockDim.x + threadIdx.x;
    if (e >= NE) return;
    float d = g_edge_d[e];
    if (d >= DCUT) return;
    int i = a[2 * e], j = a[2 * e + 1];
    float p = d * ((float)NBINS / DCUT);
    int s0 = atomicAdd(&g_cur[i], 1);
    g_slot_other[s0] = j; g_slot_pos[s0] = p;
    int s1 = atomicAdd(&g_cur[j], 1);
    g_slot_other[s1] = i; g_slot_pos[s1] = p;
}

// transpose + fp16 weights: g_wH[m][n*128+k]
__global__ void k_wconv(const float* __restrict__ win, const float* __restrict__ wout1,
                        const float* __restrict__ wout2, const float* __restrict__ wa1) {
    int idx = blockIdx.x * blockDim.x + threadIdx.x;
    int m = idx >> 14, pos = idx & 16383;
    if (m < 9) {
        int n = pos >> 7, k = pos & 127;
        const float* src = (m < 3) ? win + (size_t)m * 16384
                         : (m < 6) ? wout1 + (size_t)(m - 3) * 16384
                                   : wout2 + (size_t)(m - 6) * 16384;
        g_wH[idx] = __float2half(src[k * 128 + n]);
    } else if (m == 9 && pos < 8192) {
        int n = pos >> 7, k = pos & 127;
        g_wH[(size_t)9 * 16384 + pos] = __float2half(wa1[k * 64 + n]);
    }
}

// W(d)*C(d) table (fp16 storage)
__global__ __launch_bounds__(128) void k_table(const float* __restrict__ fw1,
                                               const float* __restrict__ fb1,
                                               const float* __restrict__ fw2,
                                               const float* __restrict__ fb2) {
    const int BPB = 16;
    int chunk = blockIdx.x % 257, t = blockIdx.x / 257;
    int b0 = chunk * BPB, tid = threadIdx.x;
    __shared__ float gsh[BPB * 52];
    __shared__ float t1s[BPB * 130];
    const float step = DCUT / (float)NBINS;
    const float wth = 5.0f / 49.0f;
    const float coef = -0.5f / (wth * wth);
    for (int i = tid; i < BPB * GG; i += 128) {
        int bb = i / GG, k = i % GG;
        float d = (float)(b0 + bb) * step;
        float x = d - 5.0f * (float)k / 49.0f;
        gsh[bb * 52 + k] = __expf(coef * x * x);
    }
    __syncthreads();
    const float* W1 = fw1 + (size_t)t * GG * 128;
    float s[BPB];
#pragma unroll
    for (int bb = 0; bb < BPB; bb++) s[bb] = 0.f;
    for (int k = 0; k < GG; k++) {
        float w = W1[k * 128 + tid];
#pragma unroll
        for (int bb = 0; bb < BPB; bb++) s[bb] = fmaf(gsh[bb * 52 + k], w, s[bb]);
    }
    float b1 = fb1[t * 128 + tid];
#pragma unroll
    for (int bb = 0; bb < BPB; bb++) t1s[bb * 130 + tid] = sspf(s[bb] + b1);
    __syncthreads();
    const float* W2 = fw2 + (size_t)t * 128 * 128;
    float o[BPB];
#pragma unroll
    for (int bb = 0; bb < BPB; bb++) o[bb] = 0.f;
    for (int k = 0; k < 128; k++) {
        float w = W2[k * 128 + tid];
#pragma unroll
        for (int bb = 0; bb < BPB; bb++) o[bb] = fmaf(t1s[bb * 130 + k], w, o[bb]);
    }
    float b2 = fb2[t * 128 + tid];
#pragma unroll
    for (int bb = 0; bb < BPB; bb++) {
        int b = b0 + bb;
        if (b <= NBINS) {
            float d = (float)b * step;
            float C = 0.5f * (cosf(d * 0.62831853072f) + 1.0f);
            g_tableH[((size_t)t * (NBINS + 1) + b) * 128 + tid] = __float2half((o[bb] + b2) * C);
        }
    }
}

// paired table: tabP[t][b][lane] = {W(b)[4half], W(b+1)[4half]} as uint4
__global__ void k_pair() {
    int idx = blockIdx.x * blockDim.x + threadIdx.x;
    int lane = idx & 31;
    int b = (idx >> 5) & (NBINS - 1);
    int t = idx >> 17;
    const uint2* src = (const uint2*)(g_tableH + (size_t)t * (NBINS + 1) * 128);
    uint2 w0 = src[(size_t)b * 32 + lane];
    uint2 w1 = src[(size_t)(b + 1) * 32 + lane];
    uint4 o;
    o.x = w0.x; o.y = w0.y; o.z = w1.x; o.w = w1.y;
    ((uint4*)g_tabP)[(size_t)(t * NBINS + b) * 32 + lane] = o;
}

// ---- fp16 mma building blocks ----
template <int ROWS>
__device__ __forceinline__ void load_h16(uint32_t* dst, const __half* src, int tid) {
#pragma unroll
    for (int i = 0; i < ROWS * 16 / 256; i++) {
        int idx = tid + i * 256;
        int row = idx >> 4, q = idx & 15;
        uint4 v = *(const uint4*)&src[(size_t)row * 128 + q * 8];
        *(uint4*)&dst[row * ASTR + q * 4] = v;
    }
}
template <int NT>
__device__ __forceinline__ void mma_tile(float acc[][NT][4], const uint32_t* As,
                                         const uint32_t* Bs, int wm, int wn, int lane) {
    uint32_t a_base = (uint32_t)__cvta_generic_to_shared(As);
    uint32_t b_base = (uint32_t)__cvta_generic_to_shared(Bs);
    int g = lane >> 3, rw = lane & 7;
    uint32_t aaddr[2];
#pragma unroll
    for (int mt = 0; mt < 2; mt++)
        aaddr[mt] = a_base +
            (uint32_t)((wm * 32 + mt * 16 + (g & 1) * 8 + rw) * (ASTR * 4) + (g >> 1) * 16);
    uint32_t baddr[NT / 2];
#pragma unroll
    for (int p = 0; p < NT / 2; p++)
        baddr[p] = b_base +
            (uint32_t)((wn * (NT * 8) + p * 16 + (g >> 1) * 8 + rw) * (ASTR * 4) + (g & 1) * 16);
#pragma unroll
    for (int ks = 0; ks < 8; ks++) {
        uint32_t af[2][4];
#pragma unroll
        for (int mt = 0; mt < 2; mt++)
            ldsm_x4(af[mt][0], af[mt][1], af[mt][2], af[mt][3], aaddr[mt] + ks * 32);
        uint32_t bf[NT][2];
#pragma unroll
        for (int p = 0; p < NT / 2; p++) {
            uint32_t r0, r1, r2, r3;
            ldsm_x4(r0, r1, r2, r3, baddr[p] + ks * 32);
            bf[2 * p][0] = r0; bf[2 * p][1] = r1;
            bf[2 * p + 1][0] = r2; bf[2 * p + 1][1] = r3;
        }
#pragma unroll
        for (int mt = 0; mt < 2; mt++)
#pragma unroll
            for (int nt = 0; nt < NT; nt++) mma_f16(acc[mt][nt], af[mt], bf[nt]);
    }
}

// h0 = r @ win[0] -> g_hbuf[0]
__global__ __launch_bounds__(256, 2) void k_mma_h(int t) {
    extern __shared__ uint32_t sm_u32[];
    uint32_t* As = sm_u32;
    uint32_t* Bs = sm_u32 + 128 * ASTR;
    int tid = threadIdx.x, lane = tid & 31, wid = tid >> 5, wm = wid & 3, wn = wid >> 2;
    load_h16<128>(As, g_rh + (size_t)blockIdx.x * 16384, tid);
    load_h16<128>(Bs, g_wH + (size_t)t * 16384, tid);
    __syncthreads();
    float acc[2][8][4] = {};
    mma_tile<8>(acc, As, Bs, wm, wn, lane);
    uint32_t* H = (uint32_t*)(g_hbuf[0] + (size_t)blockIdx.x * 16384);
#pragma unroll
    for (int mt = 0; mt < 2; mt++) {
        int r0 = wm * 32 + mt * 16 + (lane >> 2);
#pragma unroll
        for (int nt = 0; nt < 8; nt++) {
            int w = wn * 32 + nt * 4 + (lane & 3);
            H[r0 * 64 + w] = pack_h2(acc[mt][nt][0], acc[mt][nt][1]);
            H[(r0 + 8) * 64 + w] = pack_h2(acc[mt][nt][2], acc[mt][nt][3]);
        }
    }
}

__device__ __forceinline__ void agg_step(float4& A, uint4 tw, uint2 hh, float f) {
    float2 w0a = __half22float2(*(__half2*)&tw.x);
    float2 w0b = __half22float2(*(__half2*)&tw.y);
    float2 w1a = __half22float2(*(__half2*)&tw.z);
    float2 w1b = __half22float2(*(__half2*)&tw.w);
    float2 fa = __half22float2(*(__half2*)&hh.x);
    float2 fb = __half22float2(*(__half2*)&hh.y);
    A.x = fmaf(fmaf(f, w1a.x - w0a.x, w0a.x), fa.x, A.x);
    A.y = fmaf(fmaf(f, w1a.y - w0a.y, w0a.y), fa.y, A.y);
    A.z = fmaf(fmaf(f, w1b.x - w0b.x, w0b.x), fb.x, A.z);
    A.w = fmaf(fmaf(f, w1b.y - w0b.y, w0b.y), fb.y, A.w);
}

// fused per-tile step: y = gather(h[t&1]) -> smem ; r += ssp(y@W1+b1)@W2+b2 ;
// LAST==0: h[(t+1)&1] = r_new @ win[t+1] ; LAST==1: energy head.
// Double-buffered h removes the cross-CTA read/write race.
template <int LAST>
__global__ __launch_bounds__(256, 2) void k_dr(int t, const float* __restrict__ b1,
                                               const float* __restrict__ b2,
                                               const float* __restrict__ ba1,
                                               const float* __restrict__ wa2,
                                               const float* __restrict__ ba2,
                                               const int* __restrict__ mol,
                                               float* __restrict__ out) {
    extern __shared__ uint32_t sm_u32[];
    uint32_t* As = sm_u32;
    uint32_t* Bs = sm_u32 + 128 * ASTR;
    float* sred = (float*)(sm_u32 + 2 * 128 * ASTR);
    int tid = threadIdx.x, lane = tid & 31, wid = tid >> 5, wm = wid & 3, wn = wid >> 2;

    // issue W1 tile load first (overlaps with the gather below)
    load_h16<128>(Bs, g_wH + (size_t)(3 + t) * 16384, tid);

    // ---- agg phase: warp wid gathers atoms [wid*16, wid*16+16) into As ----
    {
        const uint4* tabP = ((const uint4*)g_tabP) + (size_t)t * NBINS * 32;
        const uint2* h2 = (const uint2*)g_hbuf[t & 1];
        int abase = blockIdx.x * 128 + wid * 16;
        for (int ai = 0; ai < 16; ai++) {
            int atom = abase + ai;
            int s0 = g_start[atom], s1 = g_start[atom + 1];
            float4 A0 = make_float4(0, 0, 0, 0), A1 = make_float4(0, 0, 0, 0);
            int s = s0;
            for (; s + 1 < s1; s += 2) {
                int ja = g_slot_other[s], jb = g_slot_other[s + 1];
                float pa = g_slot_pos[s], pb = g_slot_pos[s + 1];
                int ba = (int)pa, bb = (int)pb;
                uint4 twa = tabP[(size_t)ba * 32 + lane];
                uint4 twb = tabP[(size_t)bb * 32 + lane];
                uint2 ha = h2[(size_t)ja * 32 + lane];
                uint2 hb = h2[(size_t)jb * 32 + lane];
                agg_step(A0, twa, ha, pa - (float)ba);
                agg_step(A1, twb, hb, pb - (float)bb);
            }
            if (s < s1) {
                int ja = g_slot_other[s];
                float pa = g_slot_pos[s];
                int ba = (int)pa;
                uint4 twa = tabP[(size_t)ba * 32 + lane];
                uint2 ha = h2[(size_t)ja * 32 + lane];
                agg_step(A0, twa, ha, pa - (float)ba);
            }
            uint2 o;
            o.x = pack_h2(A0.x + A1.x, A0.y + A1.y);
            o.y = pack_h2(A0.z + A1.z, A0.w + A1.w);
            int row = wid * 16 + ai;
            *(uint2*)&As[row * ASTR + lane * 2] = o;
        }
    }
    __syncthreads();

    // GEMM1: U = ssp(y @ W1 + b1)
    float acc[2][8][4] = {};
    mma_tile<8>(acc, As, Bs, wm, wn, lane);
    __syncthreads();
#pragma unroll
    for (int mt = 0; mt < 2; mt++) {
        int r0 = wm * 32 + mt * 16 + (lane >> 2);
#pragma unroll
        for (int nt = 0; nt < 8; nt++) {
            int col = wn * 64 + nt * 8 + (lane & 3) * 2;
            int w = wn * 32 + nt * 4 + (lane & 3);
            float bb0 = b1[col], bb1 = b1[col + 1];
            As[r0 * ASTR + w] = pack_h2(sspf(acc[mt][nt][0] + bb0), sspf(acc[mt][nt][1] + bb1));
            As[(r0 + 8) * ASTR + w] = pack_h2(sspf(acc[mt][nt][2] + bb0), sspf(acc[mt][nt][3] + bb1));
        }
    }
    load_h16<128>(Bs, g_wH + (size_t)(6 + t) * 16384, tid);
    __syncthreads();

    // GEMM2: dr = U @ W2 + b2 ; r_new = r + dr (fp16 stream), restage into As
    float acc2[2][8][4] = {};
    mma_tile<8>(acc2, As, Bs, wm, wn, lane);
    __syncthreads();
    uint32_t* RH = (uint32_t*)(g_rh + (size_t)blockIdx.x * 16384);
#pragma unroll
    for (int mt = 0; mt < 2; mt++) {
        int r0 = wm * 32 + mt * 16 + (lane >> 2);
#pragma unroll
        for (int nt = 0; nt < 8; nt++) {
            int col = wn * 64 + nt * 8 + (lane & 3) * 2;
            int w = wn * 32 + nt * 4 + (lane & 3);
            float bb0 = b2[col], bb1 = b2[col + 1];
#pragma unroll
            for (int half = 0; half < 2; half++) {
                int rr = r0 + half * 8;
                uint32_t old = RH[rr * 64 + w];
                float2 ro = __half22float2(*(__half2*)&old);
                float v0 = ro.x + acc2[mt][nt][half * 2]     + bb0;
                float v1 = ro.y + acc2[mt][nt][half * 2 + 1] + bb1;
                uint32_t pk = pack_h2(v0, v1);
                RH[rr * 64 + w] = pk;
                As[rr * ASTR + w] = pk;
            }
        }
    }

    if (LAST == 0) {
        // GEMM3: h_{t+1} = r_new @ win[t+1] -> the OTHER h buffer
        load_h16<128>(Bs, g_wH + (size_t)(t + 1) * 16384, tid);
        __syncthreads();
        float acc3[2][8][4] = {};
        mma_tile<8>(acc3, As, Bs, wm, wn, lane);
        uint32_t* H = (uint32_t*)(g_hbuf[(t + 1) & 1] + (size_t)blockIdx.x * 16384);
#pragma unroll
        for (int mt = 0; mt < 2; mt++) {
            int r0 = wm * 32 + mt * 16 + (lane >> 2);
#pragma unroll
            for (int nt = 0; nt < 8; nt++) {
                int w = wn * 32 + nt * 4 + (lane & 3);
                H[r0 * 64 + w] = pack_h2(acc3[mt][nt][0], acc3[mt][nt][1]);
                H[(r0 + 8) * 64 + w] = pack_h2(acc3[mt][nt][2], acc3[mt][nt][3]);
            }
        }
    } else {
        // head: out[mol] += ssp(r_new @ wa1 + ba1) . wa2 + ba2
        load_h16<64>(Bs, g_wH + (size_t)9 * 16384, tid);
        if (tid < 128) sred[tid] = 0.f;
        __syncthreads();
        float acc3[2][4][4] = {};
        mma_tile<4>(acc3, As, Bs, wm, wn, lane);
#pragma unroll
        for (int mt = 0; mt < 2; mt++) {
            int r0 = wm * 32 + mt * 16 + (lane >> 2);
            float p0 = 0.f, p1 = 0.f;
#pragma unroll
            for (int nt = 0; nt < 4; nt++) {
                int col = wn * 32 + nt * 8 + (lane & 3) * 2;
                float bb0 = ba1[col], bb1 = ba1[col + 1];
                float w0 = wa2[col], w1 = wa2[col + 1];
                p0 += sspf(acc3[mt][nt][0] + bb0) * w0 + sspf(acc3[mt][nt][1] + bb1) * w1;
                p1 += sspf(acc3[mt][nt][2] + bb0) * w0 + sspf(acc3[mt][nt][3] + bb1) * w1;
            }
            atomicAdd(&sred[r0], p0);
            atomicAdd(&sred[r0 + 8], p1);
        }
        __syncthreads();
        if (tid < 128)
            atomicAdd(&out[mol[blockIdx.x * 128 + tid]], sred[tid] + ba2[0]);
    }
}

extern "C" void kernel_launch(void* const* d_in, const int* in_sizes, int n_in,
                              void* d_out, int out_size) {
    const float* xyz   = (const float*)d_in[0];
    const float* emb   = (const float*)d_in[1];
    const float* fw1   = (const float*)d_in[2];
    const float* fb1   = (const float*)d_in[3];
    const float* fw2   = (const float*)d_in[4];
    const float* fb2   = (const float*)d_in[5];
    const float* win   = (const float*)d_in[6];
    const float* wout1 = (const float*)d_in[7];
    const float* bout1 = (const float*)d_in[8];
    const float* wout2 = (const float*)d_in[9];
    const float* bout2 = (const float*)d_in[10];
    const float* wa1   = (const float*)d_in[11];
    const float* ba1   = (const float*)d_in[12];
    const float* wa2   = (const float*)d_in[13];
    const float* ba2   = (const float*)d_in[14];
    const int*   z     = (const int*)d_in[15];
    const int*   a     = (const int*)d_in[16];
    const int*   mol   = (const int*)d_in[17];
    float* out = (float*)d_out;

    const int SM_BIG = (2 * 128 * ASTR + 128) * 4;   // 70144 -> 2 CTA/SM
    cudaFuncSetAttribute(k_mma_h, cudaFuncAttributeMaxDynamicSharedMemorySize, SM_BIG);
    cudaFuncSetAttribute(k_dr<0>, cudaFuncAttributeMaxDynamicSharedMemorySize, SM_BIG);
    cudaFuncSetAttribute(k_dr<1>, cudaFuncAttributeMaxDynamicSharedMemorySize, SM_BIG);

    static cudaStream_t sA = nullptr, sB = nullptr;
    static cudaEvent_t ev0 = nullptr, evA = nullptr, evB = nullptr;
    if (!sA) {
        cudaStreamCreateWithFlags(&sA, cudaStreamNonBlocking);
        cudaStreamCreateWithFlags(&sB, cudaStreamNonBlocking);
        cudaEventCreateWithFlags(&ev0, cudaEventDisableTiming);
        cudaEventCreateWithFlags(&evA, cudaEventDisableTiming);
        cudaEventCreateWithFlags(&evB, cudaEventDisableTiming);
    }

    cudaEventRecord(ev0, 0);
    cudaStreamWaitEvent(sA, ev0, 0);
    cudaStreamWaitEvent(sB, ev0, 0);

    // branch B: edge/CSR/table prep chain (+ paired table)
    k_prep<<<NA / 256, 256, 0, sB>>>(out);
    k_edge<<<NE / 256, 256, 0, sB>>>(xyz, a);
    k_scan1<<<512, 256, 0, sB>>>();
    k_scan2<<<1, 512, 0, sB>>>();
    k_scan3<<<512, 256, 0, sB>>>();
    k_fill<<<NE / 256, 256, 0, sB>>>(a);
    k_table<<<3 * 257, 128, 0, sB>>>(fw1, fb1, fw2, fb2);
    k_pair<<<(3 * NBINS * 32) / 256, 256, 0, sB>>>();
    cudaEventRecord(evB, sB);

    // branch A: embeddings + weights + first h-GEMM
    k_embed<<<(NA * 32) / 256, 256, 0, sA>>>(emb, z);
    k_wconv<<<640, 256, 0, sA>>>(win, wout1, wout2, wa1);
    k_mma_h<<<NA / 128, 256, SM_BIG, sA>>>(0);

    cudaStreamWaitEvent(sA, evB, 0);
    for (int t = 0; t < 3; t++) {
        if (t < 2)
            k_dr<0><<<NA / 128, 256, SM_BIG, sA>>>(t, bout1 + t * 128, bout2 + t * 128,
                                                   ba1, wa2, ba2, mol, out);
        else
            k_dr<1><<<NA / 128, 256, SM_BIG, sA>>>(t, bout1 + t * 128, bout2 + t * 128,
                                                   ba1, wa2, ba2, mol, out);
    }
    cudaEventRecord(evA, sA);
    cudaStreamWaitEvent(0, evA, 0);
}

// round 17
// speedup vs baseline: 1.2459x; 1.2459x over previous
#include <cuda_runtime.h>
#include <cuda_fp16.h>
#include <stdint.h>

#define NA 131072
#define NE 524288
#define NM 2048
#define GG 50
#define NBINS 4096
#define DCUT 6.0f
#define LN2F 0.69314718056f
#define ASTR 68  // u32 words per smem row (64 data + 4 pad); 68 % 32 == 4 -> conflict-free

// ---- device scratch ----
__device__ __half g_rh[NA * 128];   // fp16 residual stream r
__device__ __half g_h[NA * 128];
__device__ __half g_y[NA * 128];
__device__ __half g_wH[10 * 128 * 128];  // transposed fp16 weights [m][n][k]
__device__ __half g_tableH[3 * (NBINS + 1) * 128];
__device__ __half g_tabP[3 * NBINS * 256];  // paired rows {W(b), W(b+1)} per lane
__device__ float g_edge_d[NE];
__device__ int   g_deg[NA];
__device__ int   g_start[NA + 1];
__device__ int   g_cur[NA];
__device__ int   g_bsum[512];
__device__ int   g_slot_other[2 * NE];
__device__ float g_slot_pos[2 * NE];

__device__ __forceinline__ float sspf(float x) {
    return fmaxf(x, 0.f) + log1pf(__expf(-fabsf(x))) - LN2F;
}
__device__ __forceinline__ uint32_t pack_h2(float a, float b) {
    __half2 p = __floats2half2_rn(a, b);
    return *(uint32_t*)&p;
}
__device__ __forceinline__ void mma_f16(float* c, const uint32_t* a, const uint32_t* b) {
    asm volatile(
        "mma.sync.aligned.m16n8k16.row.col.f32.f16.f16.f32 "
        "{%0,%1,%2,%3}, {%4,%5,%6,%7}, {%8,%9}, {%0,%1,%2,%3};"
        : "+f"(c[0]), "+f"(c[1]), "+f"(c[2]), "+f"(c[3])
        : "r"(a[0]), "r"(a[1]), "r"(a[2]), "r"(a[3]), "r"(b[0]), "r"(b[1]));
}
__device__ __forceinline__ void ldsm_x4(uint32_t& r0, uint32_t& r1, uint32_t& r2,
                                        uint32_t& r3, uint32_t addr) {
    asm volatile("ldmatrix.sync.aligned.m8n8.x4.shared.b16 {%0,%1,%2,%3}, [%4];"
                 : "=r"(r0), "=r"(r1), "=r"(r2), "=r"(r3) : "r"(addr));
}

// ---- prep kernels ----
__global__ void k_prep(float* __restrict__ out) {
    int i = blockIdx.x * blockDim.x + threadIdx.x;
    if (i < NA) g_deg[i] = 0;
    if (i < NM) out[i] = 0.f;
}
__global__ void k_embed(const float* __restrict__ emb, const int* __restrict__ z) {
    int idx = blockIdx.x * blockDim.x + threadIdx.x;
    int atom = idx >> 5, q = idx & 31;
    float4 v = ((const float4*)emb)[(size_t)z[atom] * 32 + q];
    uint2 o;
    o.x = pack_h2(v.x, v.y);
    o.y = pack_h2(v.z, v.w);
    ((uint2*)g_rh)[(size_t)atom * 32 + q] = o;
}
__global__ void k_edge(const float* __restrict__ xyz, const int* __restrict__ a) {
    int e = blockIdx.x * blockDim.x + threadIdx.x;
    if (e >= NE) return;
    int i = a[2 * e], j = a[2 * e + 1];
    float dx = xyz[3 * i] - xyz[3 * j];
    float dy = xyz[3 * i + 1] - xyz[3 * j + 1];
    float dz = xyz[3 * i + 2] - xyz[3 * j + 2];
    float d = sqrtf(dx * dx + dy * dy + dz * dz);
    g_edge_d[e] = d;
    if (d < DCUT) { atomicAdd(&g_deg[i], 1); atomicAdd(&g_deg[j], 1); }
}
__global__ void k_scan1() {
    int b = blockIdx.x, t = threadIdx.x, i = b * 256 + t;
    int lane = t & 31, w = t >> 5;
    int v = g_deg[i], s = v;
#pragma unroll
    for (int off = 1; off < 32; off <<= 1) {
        int u = __shfl_up_sync(0xffffffffu, s, off);
        if (lane >= off) s += u;
    }
    __shared__ int wsum[8];
    if (lane == 31) wsum[w] = s;
    __syncthreads();
    if (t < 8) {
        int x = wsum[t];
#pragma unroll
        for (int off = 1; off < 8; off <<= 1) {
            int u = __shfl_up_sync(0xffu, x, off);
            if (t >= off) x += u;
        }
        wsum[t] = x;
    }
    __syncthreads();
    int base = (w > 0) ? wsum[w - 1] : 0;
    g_start[i] = base + s - v;
    if (t == 255) g_bsum[b] = wsum[7];
}
__global__ void k_scan2() {
    __shared__ int sh[512];
    int t = threadIdx.x;
    int v = g_bsum[t];
    sh[t] = v;
    __syncthreads();
    for (int off = 1; off < 512; off <<= 1) {
        int u = (t >= off) ? sh[t - off] : 0;
        __syncthreads();
        sh[t] += u;
        __syncthreads();
    }
    g_bsum[t] = sh[t] - v;
    if (t == 511) g_start[NA] = sh[511];
}
__global__ void k_scan3() {
    int b = blockIdx.x, i = b * 256 + threadIdx.x;
    int s = g_start[i] + g_bsum[b];
    g_start[i] = s;
    g_cur[i] = s;
}
__global__ void k_fill(const int* __restrict__ a) {
    int e = blockIdx.x * blockDim.x + threadIdx.x;
    if (e >= NE) return;
    float d = g_edge_d[e];
    if (d >= DCUT) return;
    int i = a[2 * e], j = a[2 * e + 1];
    float p = d * ((float)NBINS / DCUT);
    int s0 = atomicAdd(&g_cur[i], 1);
    g_slot_other[s0] = j; g_slot_pos[s0] = p;
    int s1 = atomicAdd(&g_cur[j], 1);
    g_slot_other[s1] = i; g_slot_pos[s1] = p;
}

// transpose + fp16 weights: g_wH[m][n*128+k]
__global__ void k_wconv(const float* __restrict__ win, const float* __restrict__ wout1,
                        const float* __restrict__ wout2, const float* __restrict__ wa1) {
    int idx = blockIdx.x * blockDim.x + threadIdx.x;
    int m = idx >> 14, pos = idx & 16383;
    if (m < 9) {
        int n = pos >> 7, k = pos & 127;
        const float* src = (m < 3) ? win + (size_t)m * 16384
                         : (m < 6) ? wout1 + (size_t)(m - 3) * 16384
                                   : wout2 + (size_t)(m - 6) * 16384;
        g_wH[idx] = __float2half(src[k * 128 + n]);
    } else if (m == 9 && pos < 8192) {
        int n = pos >> 7, k = pos & 127;
        g_wH[(size_t)9 * 16384 + pos] = __float2half(wa1[k * 64 + n]);
    }
}

// W(d)*C(d) table (fp16 storage)
__global__ __launch_bounds__(128) void k_table(const float* __restrict__ fw1,
                                               const float* __restrict__ fb1,
                                               const float* __restrict__ fw2,
                                               const float* __restrict__ fb2) {
    const int BPB = 16;
    int chunk = blockIdx.x % 257, t = blockIdx.x / 257;
    int b0 = chunk * BPB, tid = threadIdx.x;
    __shared__ float gsh[BPB * 52];
    __shared__ float t1s[BPB * 130];
    const float step = DCUT / (float)NBINS;
    const float wth = 5.0f / 49.0f;
    const float coef = -0.5f / (wth * wth);
    for (int i = tid; i < BPB * GG; i += 128) {
        int bb = i / GG, k = i % GG;
        float d = (float)(b0 + bb) * step;
        float x = d - 5.0f * (float)k / 49.0f;
        gsh[bb * 52 + k] = __expf(coef * x * x);
    }
    __syncthreads();
    const float* W1 = fw1 + (size_t)t * GG * 128;
    float s[BPB];
#pragma unroll
    for (int bb = 0; bb < BPB; bb++) s[bb] = 0.f;
    for (int k = 0; k < GG; k++) {
        float w = W1[k * 128 + tid];
#pragma unroll
        for (int bb = 0; bb < BPB; bb++) s[bb] = fmaf(gsh[bb * 52 + k], w, s[bb]);
    }
    float b1 = fb1[t * 128 + tid];
#pragma unroll
    for (int bb = 0; bb < BPB; bb++) t1s[bb * 130 + tid] = sspf(s[bb] + b1);
    __syncthreads();
    const float* W2 = fw2 + (size_t)t * 128 * 128;
    float o[BPB];
#pragma unroll
    for (int bb = 0; bb < BPB; bb++) o[bb] = 0.f;
    for (int k = 0; k < 128; k++) {
        float w = W2[k * 128 + tid];
#pragma unroll
        for (int bb = 0; bb < BPB; bb++) o[bb] = fmaf(t1s[bb * 130 + k], w, o[bb]);
    }
    float b2 = fb2[t * 128 + tid];
#pragma unroll
    for (int bb = 0; bb < BPB; bb++) {
        int b = b0 + bb;
        if (b <= NBINS) {
            float d = (float)b * step;
            float C = 0.5f * (cosf(d * 0.62831853072f) + 1.0f);
            g_tableH[((size_t)t * (NBINS + 1) + b) * 128 + tid] = __float2half((o[bb] + b2) * C);
        }
    }
}

// paired table: tabP[t][b][lane] = {W(b)[4half], W(b+1)[4half]} as uint4
__global__ void k_pair() {
    int idx = blockIdx.x * blockDim.x + threadIdx.x;
    int lane = idx & 31;
    int b = (idx >> 5) & (NBINS - 1);
    int t = idx >> 17;
    const uint2* src = (const uint2*)(g_tableH + (size_t)t * (NBINS + 1) * 128);
    uint2 w0 = src[(size_t)b * 32 + lane];
    uint2 w1 = src[(size_t)(b + 1) * 32 + lane];
    uint4 o;
    o.x = w0.x; o.y = w0.y; o.z = w1.x; o.w = w1.y;
    ((uint4*)g_tabP)[(size_t)(t * NBINS + b) * 32 + lane] = o;
}

// ---- fp16 mma building blocks ----
template <int ROWS>
__device__ __forceinline__ void load_h16(uint32_t* dst, const __half* src, int tid) {
#pragma unroll
    for (int i = 0; i < ROWS * 16 / 256; i++) {
        int idx = tid + i * 256;
        int row = idx >> 4, q = idx & 15;
        uint4 v = *(const uint4*)&src[(size_t)row * 128 + q * 8];
        *(uint4*)&dst[row * ASTR + q * 4] = v;
    }
}
template <int NT>
__device__ __forceinline__ void mma_tile(float acc[][NT][4], const uint32_t* As,
                                         const uint32_t* Bs, int wm, int wn, int lane) {
    uint32_t a_base = (uint32_t)__cvta_generic_to_shared(As);
    uint32_t b_base = (uint32_t)__cvta_generic_to_shared(Bs);
    int g = lane >> 3, rw = lane & 7;
    uint32_t aaddr[2];
#pragma unroll
    for (int mt = 0; mt < 2; mt++)
        aaddr[mt] = a_base +
            (uint32_t)((wm * 32 + mt * 16 + (g & 1) * 8 + rw) * (ASTR * 4) + (g >> 1) * 16);
    uint32_t baddr[NT / 2];
#pragma unroll
    for (int p = 0; p < NT / 2; p++)
        baddr[p] = b_base +
            (uint32_t)((wn * (NT * 8) + p * 16 + (g >> 1) * 8 + rw) * (ASTR * 4) + (g & 1) * 16);
#pragma unroll
    for (int ks = 0; ks < 8; ks++) {
        uint32_t af[2][4];
#pragma unroll
        for (int mt = 0; mt < 2; mt++)
            ldsm_x4(af[mt][0], af[mt][1], af[mt][2], af[mt][3], aaddr[mt] + ks * 32);
        uint32_t bf[NT][2];
#pragma unroll
        for (int p = 0; p < NT / 2; p++) {
            uint32_t r0, r1, r2, r3;
            ldsm_x4(r0, r1, r2, r3, baddr[p] + ks * 32);
            bf[2 * p][0] = r0; bf[2 * p][1] = r1;
            bf[2 * p + 1][0] = r2; bf[2 * p + 1][1] = r3;
        }
#pragma unroll
        for (int mt = 0; mt < 2; mt++)
#pragma unroll
            for (int nt = 0; nt < NT; nt++) mma_f16(acc[mt][nt], af[mt], bf[nt]);
    }
}

// h = r @ win[0]   (t=0 only; later h's fused into k_dr)
__global__ __launch_bounds__(256, 2) void k_mma_h(int t) {
    extern __shared__ uint32_t sm_u32[];
    uint32_t* As = sm_u32;
    uint32_t* Bs = sm_u32 + 128 * ASTR;
    int tid = threadIdx.x, lane = tid & 31, wid = tid >> 5, wm = wid & 3, wn = wid >> 2;
    load_h16<128>(As, g_rh + (size_t)blockIdx.x * 16384, tid);
    load_h16<128>(Bs, g_wH + (size_t)t * 16384, tid);
    __syncthreads();
    float acc[2][8][4] = {};
    mma_tile<8>(acc, As, Bs, wm, wn, lane);
    uint32_t* H = (uint32_t*)(g_h + (size_t)blockIdx.x * 16384);
#pragma unroll
    for (int mt = 0; mt < 2; mt++) {
        int r0 = wm * 32 + mt * 16 + (lane >> 2);
#pragma unroll
        for (int nt = 0; nt < 8; nt++) {
            int w = wn * 32 + nt * 4 + (lane & 3);
            H[r0 * 64 + w] = pack_h2(acc[mt][nt][0], acc[mt][nt][1]);
            H[(r0 + 8) * 64 + w] = pack_h2(acc[mt][nt][2], acc[mt][nt][3]);
        }
    }
}

// fused: r += ssp(y@W1+b1)@W2+b2 ; then LAST==0: h=r_new@win[t+1] ; LAST==1: head
template <int LAST>
__global__ __launch_bounds__(256, 2) void k_dr(int t, const float* __restrict__ b1,
                                               const float* __restrict__ b2,
                                               const float* __restrict__ ba1,
                                               const float* __restrict__ wa2,
                                               const float* __restrict__ ba2,
                                               const int* __restrict__ mol,
                                               float* __restrict__ out) {
    extern __shared__ uint32_t sm_u32[];
    uint32_t* As = sm_u32;
    uint32_t* Bs = sm_u32 + 128 * ASTR;
    float* sred = (float*)(sm_u32 + 2 * 128 * ASTR);
    int tid = threadIdx.x, lane = tid & 31, wid = tid >> 5, wm = wid & 3, wn = wid >> 2;

    load_h16<128>(As, g_y + (size_t)blockIdx.x * 16384, tid);
    load_h16<128>(Bs, g_wH + (size_t)(3 + t) * 16384, tid);
    __syncthreads();
    float acc[2][8][4] = {};
    mma_tile<8>(acc, As, Bs, wm, wn, lane);
    __syncthreads();
#pragma unroll
    for (int mt = 0; mt < 2; mt++) {
        int r0 = wm * 32 + mt * 16 + (lane >> 2);
#pragma unroll
        for (int nt = 0; nt < 8; nt++) {
            int col = wn * 64 + nt * 8 + (lane & 3) * 2;
            int w = wn * 32 + nt * 4 + (lane & 3);
            float bb0 = b1[col], bb1 = b1[col + 1];
            As[r0 * ASTR + w] = pack_h2(sspf(acc[mt][nt][0] + bb0), sspf(acc[mt][nt][1] + bb1));
            As[(r0 + 8) * ASTR + w] = pack_h2(sspf(acc[mt][nt][2] + bb0), sspf(acc[mt][nt][3] + bb1));
        }
    }
    load_h16<128>(Bs, g_wH + (size_t)(6 + t) * 16384, tid);
    __syncthreads();

    float acc2[2][8][4] = {};
    mma_tile<8>(acc2, As, Bs, wm, wn, lane);
    __syncthreads();
    uint32_t* RH = (uint32_t*)(g_rh + (size_t)blockIdx.x * 16384);
#pragma unroll
    for (int mt = 0; mt < 2; mt++) {
        int r0 = wm * 32 + mt * 16 + (lane >> 2);
#pragma unroll
        for (int nt = 0; nt < 8; nt++) {
            int col = wn * 64 + nt * 8 + (lane & 3) * 2;
            int w = wn * 32 + nt * 4 + (lane & 3);
            float bb0 = b2[col], bb1 = b2[col + 1];
#pragma unroll
            for (int half = 0; half < 2; half++) {
                int rr = r0 + half * 8;
                uint32_t old = RH[rr * 64 + w];
                float2 ro = __half22float2(*(__half2*)&old);
                float v0 = ro.x + acc2[mt][nt][half * 2]     + bb0;
                float v1 = ro.y + acc2[mt][nt][half * 2 + 1] + bb1;
                uint32_t pk = pack_h2(v0, v1);
                RH[rr * 64 + w] = pk;
                As[rr * ASTR + w] = pk;
            }
        }
    }

    if (LAST == 0) {
        load_h16<128>(Bs, g_wH + (size_t)(t + 1) * 16384, tid);
        __syncthreads();
        float acc3[2][8][4] = {};
        mma_tile<8>(acc3, As, Bs, wm, wn, lane);
        uint32_t* H = (uint32_t*)(g_h + (size_t)blockIdx.x * 16384);
#pragma unroll
        for (int mt = 0; mt < 2; mt++) {
            int r0 = wm * 32 + mt * 16 + (lane >> 2);
#pragma unroll
            for (int nt = 0; nt < 8; nt++) {
                int w = wn * 32 + nt * 4 + (lane & 3);
                H[r0 * 64 + w] = pack_h2(acc3[mt][nt][0], acc3[mt][nt][1]);
                H[(r0 + 8) * 64 + w] = pack_h2(acc3[mt][nt][2], acc3[mt][nt][3]);
            }
        }
    } else {
        load_h16<64>(Bs, g_wH + (size_t)9 * 16384, tid);
        if (tid < 128) sred[tid] = 0.f;
        __syncthreads();
        float acc3[2][4][4] = {};
        mma_tile<4>(acc3, As, Bs, wm, wn, lane);
#pragma unroll
        for (int mt = 0; mt < 2; mt++) {
            int r0 = wm * 32 + mt * 16 + (lane >> 2);
            float p0 = 0.f, p1 = 0.f;
#pragma unroll
            for (int nt = 0; nt < 4; nt++) {
                int col = wn * 32 + nt * 8 + (lane & 3) * 2;
                float bb0 = ba1[col], bb1 = ba1[col + 1];
                float w0 = wa2[col], w1 = wa2[col + 1];
                p0 += sspf(acc3[mt][nt][0] + bb0) * w0 + sspf(acc3[mt][nt][1] + bb1) * w1;
                p1 += sspf(acc3[mt][nt][2] + bb0) * w0 + sspf(acc3[mt][nt][3] + bb1) * w1;
            }
            atomicAdd(&sred[r0], p0);
            atomicAdd(&sred[r0 + 8], p1);
        }
        __syncthreads();
        if (tid < 128)
            atomicAdd(&out[mol[blockIdx.x * 128 + tid]], sred[tid] + ba2[0]);
    }
}

// ---- aggregation: paired table + 2-way unrolled gather (1 warp/atom) ----
__device__ __forceinline__ void agg_step(float4& A, uint4 tw, uint2 hh, float f) {
    float2 w0a = __half22float2(*(__half2*)&tw.x);
    float2 w0b = __half22float2(*(__half2*)&tw.y);
    float2 w1a = __half22float2(*(__half2*)&tw.z);
    float2 w1b = __half22float2(*(__half2*)&tw.w);
    float2 fa = __half22float2(*(__half2*)&hh.x);
    float2 fb = __half22float2(*(__half2*)&hh.y);
    A.x = fmaf(fmaf(f, w1a.x - w0a.x, w0a.x), fa.x, A.x);
    A.y = fmaf(fmaf(f, w1a.y - w0a.y, w0a.y), fa.y, A.y);
    A.z = fmaf(fmaf(f, w1b.x - w0b.x, w0b.x), fb.x, A.z);
    A.w = fmaf(fmaf(f, w1b.y - w0b.y, w0b.y), fb.y, A.w);
}
__global__ __launch_bounds__(256) void k_agg(int t) {
    int gid = blockIdx.x * blockDim.x + threadIdx.x;
    int atom = gid >> 5, lane = gid & 31;
    const uint4* tabP = ((const uint4*)g_tabP) + (size_t)t * NBINS * 32;
    const uint2* h2 = (const uint2*)g_h;
    int s0 = g_start[atom], s1 = g_start[atom + 1];
    float4 A0 = make_float4(0, 0, 0, 0), A1 = make_float4(0, 0, 0, 0);
    int s = s0;
    for (; s + 1 < s1; s += 2) {
        int ja = g_slot_other[s], jb = g_slot_other[s + 1];
        float pa = g_slot_pos[s], pb = g_slot_pos[s + 1];
        int ba = (int)pa, bb = (int)pb;
        uint4 twa = tabP[(size_t)ba * 32 + lane];
        uint4 twb = tabP[(size_t)bb * 32 + lane];
        uint2 ha = h2[(size_t)ja * 32 + lane];
        uint2 hb = h2[(size_t)jb * 32 + lane];
        agg_step(A0, twa, ha, pa - (float)ba);
        agg_step(A1, twb, hb, pb - (float)bb);
    }
    if (s < s1) {
        int ja = g_slot_other[s];
        float pa = g_slot_pos[s];
        int ba = (int)pa;
        uint4 twa = tabP[(size_t)ba * 32 + lane];
        uint2 ha = h2[(size_t)ja * 32 + lane];
        agg_step(A0, twa, ha, pa - (float)ba);
    }
    uint2 o;
    o.x = pack_h2(A0.x + A1.x, A0.y + A1.y);
    o.y = pack_h2(A0.z + A1.z, A0.w + A1.w);
    ((uint2*)g_y)[(size_t)atom * 32 + lane] = o;
}

extern "C" void kernel_launch(void* const* d_in, const int* in_sizes, int n_in,
                              void* d_out, int out_size) {
    const float* xyz   = (const float*)d_in[0];
    const float* emb   = (const float*)d_in[1];
    const float* fw1   = (const float*)d_in[2];
    const float* fb1   = (const float*)d_in[3];
    const float* fw2   = (const float*)d_in[4];
    const float* fb2   = (const float*)d_in[5];
    const float* win   = (const float*)d_in[6];
    const float* wout1 = (const float*)d_in[7];
    const float* bout1 = (const float*)d_in[8];
    const float* wout2 = (const float*)d_in[9];
    const float* bout2 = (const float*)d_in[10];
    const float* wa1   = (const float*)d_in[11];
    const float* ba1   = (const float*)d_in[12];
    const float* wa2   = (const float*)d_in[13];
    const float* ba2   = (const float*)d_in[14];
    const int*   z     = (const int*)d_in[15];
    const int*   a     = (const int*)d_in[16];
    const int*   mol   = (const int*)d_in[17];
    float* out = (float*)d_out;

    const int SM_BIG = (2 * 128 * ASTR + 128) * 4;   // 70144 -> 2 CTA/SM
    cudaFuncSetAttribute(k_mma_h, cudaFuncAttributeMaxDynamicSharedMemorySize, SM_BIG);
    cudaFuncSetAttribute(k_dr<0>, cudaFuncAttributeMaxDynamicSharedMemorySize, SM_BIG);
    cudaFuncSetAttribute(k_dr<1>, cudaFuncAttributeMaxDynamicSharedMemorySize, SM_BIG);

    static cudaStream_t sA = nullptr, sB = nullptr, sC = nullptr;
    static cudaEvent_t ev0 = nullptr, evA = nullptr, evB = nullptr, evC = nullptr, evW = nullptr;
    if (!sA) {
        cudaStreamCreateWithFlags(&sA, cudaStreamNonBlocking);
        cudaStreamCreateWithFlags(&sB, cudaStreamNonBlocking);
        cudaStreamCreateWithFlags(&sC, cudaStreamNonBlocking);
        cudaEventCreateWithFlags(&ev0, cudaEventDisableTiming);
        cudaEventCreateWithFlags(&evA, cudaEventDisableTiming);
        cudaEventCreateWithFlags(&evB, cudaEventDisableTiming);
        cudaEventCreateWithFlags(&evC, cudaEventDisableTiming);
        cudaEventCreateWithFlags(&evW, cudaEventDisableTiming);
    }

    cudaEventRecord(ev0, 0);
    cudaStreamWaitEvent(sA, ev0, 0);
    cudaStreamWaitEvent(sB, ev0, 0);
    cudaStreamWaitEvent(sC, ev0, 0);

    // stream C: weight conversion + filter table (independent of edges)
    k_wconv<<<640, 256, 0, sC>>>(win, wout1, wout2, wa1);
    cudaEventRecord(evW, sC);
    k_table<<<3 * 257, 128, 0, sC>>>(fw1, fb1, fw2, fb2);
    k_pair<<<(3 * NBINS * 32) / 256, 256, 0, sC>>>();
    cudaEventRecord(evC, sC);

    // stream B: edge/CSR chain
    k_prep<<<NA / 256, 256, 0, sB>>>(out);
    k_edge<<<NE / 256, 256, 0, sB>>>(xyz, a);
    k_scan1<<<512, 256, 0, sB>>>();
    k_scan2<<<1, 512, 0, sB>>>();
    k_scan3<<<512, 256, 0, sB>>>();
    k_fill<<<NE / 256, 256, 0, sB>>>(a);
    cudaEventRecord(evB, sB);

    // stream A: embeddings, then (after wconv) first h-GEMM
    k_embed<<<(NA * 32) / 256, 256, 0, sA>>>(emb, z);
    cudaStreamWaitEvent(sA, evW, 0);
    k_mma_h<<<NA / 128, 256, SM_BIG, sA>>>(0);

    // join everything into stream A for the t-loop
    cudaStreamWaitEvent(sA, evB, 0);
    cudaStreamWaitEvent(sA, evC, 0);
    for (int t = 0; t < 3; t++) {
        k_agg<<<(NA * 32) / 256, 256, 0, sA>>>(t);
        if (t < 2)
            k_dr<0><<<NA / 128, 256, SM_BIG, sA>>>(t, bout1 + t * 128, bout2 + t * 128,
                                                   ba1, wa2, ba2, mol, out);
        else
            k_dr<1><<<NA / 128, 256, SM_BIG, sA>>>(t, bout1 + t * 128, bout2 + t * 128,
                                                   ba1, wa2, ba2, mol, out);
    }
    cudaEventRecord(evA, sA);
    cudaStreamWaitEvent(0, evA, 0);
}